// round 2
// baseline (speedup 1.0000x reference)
#include <cuda_runtime.h>
#include <cuda_bf16.h>
#include <cstdint>

typedef unsigned long long ull;

#define EPSF 1e-5f

// ---------------- scratch ----------------
__device__ float g_P[(size_t)256 * 208 * 16];   // [c][m][a16], 0.5 folded
__device__ float g_Pb[208 * 16];                // [m][a16], 0.5 folded
__device__ float g_W1T[256 * 128];              // [c][f], BN-scale folded
__device__ float g_bf[128];                     // folded bias
__device__ float g_att[(size_t)13312 * 256];    // attention out, row=a*1024+b

// ---------------- f32x2 helpers ----------------
__device__ __forceinline__ ull fma2(ull a, ull b, ull c) {
    ull d;
    asm("fma.rn.f32x2 %0, %1, %2, %3;" : "=l"(d) : "l"(a), "l"(b), "l"(c));
    return d;
}
__device__ __forceinline__ ull dup2(float v) {
    ull d; unsigned r = __float_as_uint(v);
    asm("mov.b64 %0, {%1, %1};" : "=l"(d) : "r"(r));
    return d;
}
__device__ __forceinline__ float lo32(ull a) { return __uint_as_float((unsigned)(a & 0xffffffffull)); }
__device__ __forceinline__ float hi32(ull a) { return __uint_as_float((unsigned)(a >> 32)); }

// ================= fold Q into Wk =================
__global__ void k_precompP(const float* __restrict__ Q,
                           const float* __restrict__ Wk,
                           const float* __restrict__ bk) {
    int m = blockIdx.x;            // 0..207
    int c = threadIdx.x;           // 0..255
    int hk = m / 13;
    const float* qp = Q + m * 4;   // Q[(m>>4)][m&15][:]
    float q0 = qp[0], q1 = qp[1], q2 = qp[2], q3 = qp[3];
    float* dst = g_P + (size_t)c * 3328 + m * 16;
    #pragma unroll
    for (int a = 0; a < 13; ++a) {
        const float* w = Wk + (size_t)(a * 64 + hk * 4) * 256 + c;
        float s = q0 * w[0] + q1 * w[256] + q2 * w[512] + q3 * w[768];
        dst[a] = 0.5f * s;
    }
    dst[13] = dst[14] = dst[15] = 0.f;
    if (c < 16) {
        float v = 0.f;
        if (c < 13) {
            const float* bb = bk + c * 64 + hk * 4;
            v = 0.5f * (q0 * bb[0] + q1 * bb[1] + q2 * bb[2] + q3 * bb[3]);
        }
        g_Pb[m * 16 + c] = v;
    }
}

// ================= fold BN into W1, transpose =================
__global__ void k_foldW1(const float* __restrict__ W1, const float* __restrict__ b1,
                         const float* __restrict__ bnw, const float* __restrict__ bnb,
                         const float* __restrict__ bnrm, const float* __restrict__ bnrv) {
    int f = blockIdx.x;    // 0..127
    int c = threadIdx.x;   // 0..255
    float s = bnw[f] * rsqrtf(bnrv[f] + EPSF);
    g_W1T[c * 128 + f] = W1[f * 256 + c] * s;
    if (c == 0) g_bf[f] = b1[f] * s + bnb[f] - bnrm[f] * s;
}

// ================= fused conv + GN + logits + softmax + AV =================
// smem float offsets:
#define SX_OFF   0
#define VT_OFF   608                    // [256][68]
#define PB_OFF   (VT_OFF + 256*68)      // 8 warps x 64
#define PCH_OFF  (PB_OFF + 512)         // [16][128]
#define MS_OFF   (PCH_OFF + 2048)       // float2 [32 tp][516 col]
#define SMEM_ATT_FLOATS (MS_OFF + 33024)
#define SMEM_ATT_BYTES  (SMEM_ATT_FLOATS * 4)

__global__ void __launch_bounds__(256, 1) k_attention(
    const float* __restrict__ x, const float* __restrict__ Wc,
    const float* __restrict__ bc, const float* __restrict__ ginw,
    const float* __restrict__ ginb) {
    extern __shared__ float sm[];
    float* sx  = sm + SX_OFF;
    float* vTf = sm + VT_OFF;
    float* pbuf = sm + PB_OFF;
    float* Pch = sm + PCH_OFF;
    float* MsF = sm + MS_OFF;
    const int tid = threadIdx.x;
    const int b = blockIdx.x;

    // stage x[b] (600 floats)
    for (int i = tid; i < 150; i += 256)
        ((float4*)sx)[i] = ((const float4*)(x + (size_t)b * 600))[i];
    __syncthreads();

    // ---- conv1x1 + GroupNorm(16 groups), thread = channel ----
    {
        const int c = tid;
        float wr[10];
        #pragma unroll
        for (int i = 0; i < 10; ++i) wr[i] = Wc[c * 10 + i];
        const float bb = bc[c];
        float s1 = 0.f, s2 = 0.f;
        float* vrow = vTf + c * 68;
        #pragma unroll 4
        for (int t = 0; t < 60; ++t) {
            const float* xr = sx + t * 10;
            float h = bb;
            #pragma unroll
            for (int i = 0; i < 10; ++i) h = fmaf(wr[i], xr[i], h);
            vrow[t] = h; s1 += h; s2 = fmaf(h, h, s2);
        }
        #pragma unroll
        for (int o = 8; o; o >>= 1) {
            s1 += __shfl_xor_sync(0xffffffffu, s1, o);
            s2 += __shfl_xor_sync(0xffffffffu, s2, o);
        }
        float mean = s1 * (1.f / 960.f);
        float var = s2 * (1.f / 960.f) - mean * mean;
        float sc = ginw[c] * rsqrtf(var + EPSF);
        float sh = ginb[c] - mean * sc;
        #pragma unroll 4
        for (int t = 0; t < 60; ++t) vrow[t] = fmaf(vrow[t], sc, sh);
        vrow[60] = vrow[61] = vrow[62] = vrow[63] = 0.f;
    }

    const int e0 = (b * 13) >> 10;
    const int e12 = (b * 13 + 12) >> 10;
    const int nchunks = (e0 == e12) ? 2 : 4;
    const int tg = tid >> 5;       // warp id = t-group (8 t's)
    const int lane = tid & 31;     // 4 cols each

    // ---- GEMM: Ms[t][col] = sum_c v[t][c] * P[c][col] ----
    for (int chunk = 0; chunk < nchunks; ++chunk) {
        const int col0 = chunk * 128;
        ull acc[4][4];
        #pragma unroll
        for (int i = 0; i < 4; ++i)
            #pragma unroll
            for (int j = 0; j < 4; ++j) acc[i][j] = 0ull;

        for (int c0 = 0; c0 < 256; c0 += 16) {
            __syncthreads();
            // stage P chunk [16 c][128 col]
            #pragma unroll
            for (int rr = 0; rr < 2; ++rr) {
                int q = tid + rr * 256;
                int c = q >> 5, s = (q >> 2) & 7, fq = q & 3;
                int S = (col0 >> 4) + s;
                int mm = (S < 16) ? (S * 13 + e0) : ((S - 16) * 13 + e0 + 1);
                float4 pv = *(const float4*)(g_P + (size_t)(c0 + c) * 3328 + mm * 16 + fq * 4);
                *(float4*)(Pch + c * 128 + s * 16 + fq * 4) = pv;
            }
            __syncthreads();
            #pragma unroll
            for (int kk = 0; kk < 16; ++kk) {
                const float* vb = vTf + (c0 + kk) * 68 + tg * 8;
                ull v0 = *(const ull*)(vb);
                ull v1 = *(const ull*)(vb + 2);
                ull v2 = *(const ull*)(vb + 4);
                ull v3 = *(const ull*)(vb + 6);
                float4 pp = *(const float4*)(Pch + kk * 128 + lane * 4);
                ull p0 = dup2(pp.x), p1 = dup2(pp.y), p2 = dup2(pp.z), p3 = dup2(pp.w);
                acc[0][0] = fma2(v0, p0, acc[0][0]);
                acc[0][1] = fma2(v0, p1, acc[0][1]);
                acc[0][2] = fma2(v0, p2, acc[0][2]);
                acc[0][3] = fma2(v0, p3, acc[0][3]);
                acc[1][0] = fma2(v1, p0, acc[1][0]);
                acc[1][1] = fma2(v1, p1, acc[1][1]);
                acc[1][2] = fma2(v1, p2, acc[1][2]);
                acc[1][3] = fma2(v1, p3, acc[1][3]);
                acc[2][0] = fma2(v2, p0, acc[2][0]);
                acc[2][1] = fma2(v2, p1, acc[2][1]);
                acc[2][2] = fma2(v2, p2, acc[2][2]);
                acc[2][3] = fma2(v2, p3, acc[2][3]);
                acc[3][0] = fma2(v3, p0, acc[3][0]);
                acc[3][1] = fma2(v3, p1, acc[3][1]);
                acc[3][2] = fma2(v3, p2, acc[3][2]);
                acc[3][3] = fma2(v3, p3, acc[3][3]);
            }
        }
        // write Ms (float2 over t-pairs)
        #pragma unroll
        for (int i = 0; i < 4; ++i) {
            int tp = tg * 4 + i;
            #pragma unroll
            for (int j = 0; j < 4; ++j) {
                int col = col0 + lane * 4 + j;
                *(ull*)(MsF + 2 * (tp * 516 + col)) = acc[i][j];
            }
        }
    }
    __syncthreads();

    // ---- softmax + AV epilogue: one warp per row, 26 iters ----
    const int w = tg;
    for (int it = 0; it < 26; ++it) {
        int r = it * 8 + w;                 // 0..207
        int hk = r / 13;
        int j = r - hk * 13;
        int e = (b * 13 + j) >> 10;
        int m = hk * 13 + e;
        int colb = (hk + ((e - e0) << 4)) * 16;
        int val = j * 240 + lane * 4;
        int t = val / 52;
        int a = (val - t * 52) >> 2;
        float l1 = MsF[2 * ((t >> 1) * 516 + colb + a) + (t & 1)] + g_Pb[m * 16 + a];
        float l2 = -1e30f;
        if (lane < 28) {
            int val2 = val + 128;
            int t2 = val2 / 52;
            int a2 = (val2 - t2 * 52) >> 2;
            l2 = MsF[2 * ((t2 >> 1) * 516 + colb + a2) + (t2 & 1)] + g_Pb[m * 16 + a2];
        }
        float mx = fmaxf(l1, l2);
        #pragma unroll
        for (int o = 16; o; o >>= 1) mx = fmaxf(mx, __shfl_xor_sync(0xffffffffu, mx, o));
        float x1 = __expf(l1 - mx);
        float x2 = (lane < 28) ? __expf(l2 - mx) : 0.f;
        float sum = x1 + x2;
        #pragma unroll
        for (int o = 16; o; o >>= 1) sum += __shfl_xor_sync(0xffffffffu, sum, o);
        float inv = 1.f / sum;
        pbuf[w * 64 + lane] = x1 * inv;
        if (lane < 28) pbuf[w * 64 + 32 + lane] = x2 * inv;
        __syncwarp();
        // AV: lanes 0..15 sum t 0..29, lanes 16..31 sum t 30..59
        int dh = lane & 15;
        int toff = (lane >> 4) * 30;
        const float* vcol = vTf + (hk * 16 + dh) * 68 + toff;
        const float* pb = pbuf + w * 64 + toff;
        float acc = 0.f;
        #pragma unroll 6
        for (int tt = 0; tt < 30; ++tt) acc = fmaf(pb[tt], vcol[tt], acc);
        acc += __shfl_xor_sync(0xffffffffu, acc, 16);
        if (lane < 16) {
            int bq = (b * 13 + j) & 1023;
            g_att[(size_t)((m >> 4) * 1024 + bq) * 256 + ((m & 15) << 4) + dh] = acc;
        }
        __syncwarp();
    }
}

// ================= MLP + BN + ReLU + GroupNorm + permute =================
#define SW_OFF  0                    // [256][132]
#define SO_OFF  (256*132)            // [32][260]
#define SBF_OFF (SO_OFF + 32*260)
#define SGW_OFF (SBF_OFF + 128)
#define SGB_OFF (SGW_OFF + 128)
#define SMEM_MLP_FLOATS (SGB_OFF + 128)
#define SMEM_MLP_BYTES  (SMEM_MLP_FLOATS * 4)

__global__ void __launch_bounds__(256, 1) k_mlp(const float* __restrict__ gow,
                                                const float* __restrict__ gob,
                                                float* __restrict__ out) {
    extern __shared__ float sm[];
    float* sW = sm + SW_OFF;
    float* sO = sm + SO_OFF;
    float* sBF = sm + SBF_OFF;
    float* sGW = sm + SGW_OFF;
    float* sGB = sm + SGB_OFF;
    const int tid = threadIdx.x;
    const int row0 = blockIdx.x * 32;

    for (int i = tid; i < 32768; i += 256) sW[(i >> 7) * 132 + (i & 127)] = g_W1T[i];
    for (int i = tid; i < 8192; i += 256) sO[(i >> 8) * 260 + (i & 255)] = g_att[(size_t)row0 * 256 + i];
    if (tid < 128) { sBF[tid] = g_bf[tid]; sGW[tid] = gow[tid]; sGB[tid] = gob[tid]; }
    __syncthreads();

    const int rl = tid >> 3;       // row 0..31
    const int fg = tid & 7;        // f pairs: f = 16k + fg*2 + {0,1}
    ull acc[8];
    #pragma unroll
    for (int k = 0; k < 8; ++k) acc[k] = 0ull;
    const float* orow = sO + rl * 260;
    for (int c = 0; c < 256; ++c) {
        ull od = dup2(orow[c]);
        const float* wr = sW + c * 132 + fg * 2;
        #pragma unroll
        for (int k = 0; k < 8; ++k)
            acc[k] = fma2(od, *(const ull*)(wr + 16 * k), acc[k]);
    }

    // bias + relu
    float y0[8], y1[8];
    #pragma unroll
    for (int k = 0; k < 8; ++k) {
        int f = 16 * k + fg * 2;
        y0[k] = fmaxf(lo32(acc[k]) + sBF[f], 0.f);
        y1[k] = fmaxf(hi32(acc[k]) + sBF[f + 1], 0.f);
    }
    // GroupNorm (groups of 8 = 4 threads x 2 vals within fg-quad)
    int r = row0 + rl;
    float* orow_out = out + (size_t)((r & 1023) * 13 + (r >> 10)) * 128;
    #pragma unroll
    for (int k = 0; k < 8; ++k) {
        float s = y0[k] + y1[k];
        float s2 = y0[k] * y0[k] + y1[k] * y1[k];
        s += __shfl_xor_sync(0xffffffffu, s, 1);
        s2 += __shfl_xor_sync(0xffffffffu, s2, 1);
        s += __shfl_xor_sync(0xffffffffu, s, 2);
        s2 += __shfl_xor_sync(0xffffffffu, s2, 2);
        float mean = s * 0.125f;
        float var = s2 * 0.125f - mean * mean;
        float sc = rsqrtf(var + EPSF);
        int f = 16 * k + fg * 2;
        float o0 = (y0[k] - mean) * sc * sGW[f] + sGB[f];
        float o1 = (y1[k] - mean) * sc * sGW[f + 1] + sGB[f + 1];
        float2 ov = make_float2(o0, o1);
        *(float2*)(orow_out + f) = ov;
    }
}

// ================= launch =================
extern "C" void kernel_launch(void* const* d_in, const int* in_sizes, int n_in,
                              void* d_out, int out_size) {
    (void)in_sizes; (void)n_in; (void)out_size;
    const float* x    = (const float*)d_in[0];
    const float* Wc   = (const float*)d_in[1];
    const float* bc   = (const float*)d_in[2];
    const float* ginw = (const float*)d_in[3];
    const float* ginb = (const float*)d_in[4];
    const float* Q    = (const float*)d_in[5];
    const float* Wk   = (const float*)d_in[6];
    const float* bk   = (const float*)d_in[7];
    const float* W1   = (const float*)d_in[8];
    const float* b1   = (const float*)d_in[9];
    const float* bnw  = (const float*)d_in[10];
    const float* bnb  = (const float*)d_in[11];
    const float* bnrm = (const float*)d_in[12];
    const float* bnrv = (const float*)d_in[13];
    const float* gow  = (const float*)d_in[14];
    const float* gob  = (const float*)d_in[15];
    float* out = (float*)d_out;

    cudaFuncSetAttribute(k_attention, cudaFuncAttributeMaxDynamicSharedMemorySize, SMEM_ATT_BYTES);
    cudaFuncSetAttribute(k_mlp, cudaFuncAttributeMaxDynamicSharedMemorySize, SMEM_MLP_BYTES);

    k_precompP<<<208, 256>>>(Q, Wk, bk);
    k_foldW1<<<128, 256>>>(W1, b1, bnw, bnb, bnrm, bnrv);
    k_attention<<<1024, 256, SMEM_ATT_BYTES>>>(x, Wc, bc, ginw, ginb);
    k_mlp<<<416, 256, SMEM_MLP_BYTES>>>(gow, gob, out);
}

// round 3
// speedup vs baseline: 1.4725x; 1.4725x over previous
#include <cuda_runtime.h>
#include <cuda_bf16.h>
#include <cstdint>

typedef unsigned long long ull;

#define EPSF 1e-5f

// ---------------- scratch ----------------
__device__ float g_P[(size_t)256 * 208 * 16];   // [c][m][a16], 0.5 folded
__device__ float g_Pb[208 * 16];                // [m][a16], 0.5 folded
__device__ float g_W1T[256 * 128];              // [c][f], BN-scale folded
__device__ float g_bf[128];                     // folded bias
__device__ float g_att[(size_t)13312 * 256];    // attention out, row = a*1024 + b

// ---------------- f32x2 helpers ----------------
__device__ __forceinline__ ull fma2(ull a, ull b, ull c) {
    ull d;
    asm("fma.rn.f32x2 %0, %1, %2, %3;" : "=l"(d) : "l"(a), "l"(b), "l"(c));
    return d;
}
__device__ __forceinline__ ull dup2(float v) {
    ull d; unsigned r = __float_as_uint(v);
    asm("mov.b64 %0, {%1, %1};" : "=l"(d) : "r"(r));
    return d;
}
__device__ __forceinline__ float lo32(ull a) { return __uint_as_float((unsigned)(a & 0xffffffffull)); }
__device__ __forceinline__ float hi32(ull a) { return __uint_as_float((unsigned)(a >> 32)); }

// ================= fold Q into Wk =================
__global__ void k_precompP(const float* __restrict__ Q,
                           const float* __restrict__ Wk,
                           const float* __restrict__ bk) {
    int m = blockIdx.x;            // 0..207
    int c = threadIdx.x;           // 0..255
    int hk = m / 13;
    const float* qp = Q + m * 4;
    float q0 = qp[0], q1 = qp[1], q2 = qp[2], q3 = qp[3];
    float* dst = g_P + (size_t)c * 3328 + m * 16;
    #pragma unroll
    for (int a = 0; a < 13; ++a) {
        const float* w = Wk + (size_t)(a * 64 + hk * 4) * 256 + c;
        float s = q0 * w[0] + q1 * w[256] + q2 * w[512] + q3 * w[768];
        dst[a] = 0.5f * s;
    }
    dst[13] = dst[14] = dst[15] = 0.f;
    if (c < 16) {
        float v = 0.f;
        if (c < 13) {
            const float* bb = bk + c * 64 + hk * 4;
            v = 0.5f * (q0 * bb[0] + q1 * bb[1] + q2 * bb[2] + q3 * bb[3]);
        }
        g_Pb[m * 16 + c] = v;
    }
}

// ================= fold BN into W1, transpose =================
__global__ void k_foldW1(const float* __restrict__ W1, const float* __restrict__ b1,
                         const float* __restrict__ bnw, const float* __restrict__ bnb,
                         const float* __restrict__ bnrm, const float* __restrict__ bnrv) {
    int f = blockIdx.x;    // 0..127
    int c = threadIdx.x;   // 0..255
    float s = bnw[f] * rsqrtf(bnrv[f] + EPSF);
    g_W1T[c * 128 + f] = W1[f * 256 + c] * s;
    if (c == 0) g_bf[f] = b1[f] * s + bnb[f] - bnrm[f] * s;
}

// ================= fused conv + GN + logits + softmax + AV =================
// smem layout (floats):
#define VT_STRIDE 66
#define SX_OFF   0                               // 600
#define VT_OFF   600                             // 256*66 = 16896
#define PB_OFF   (VT_OFF + 256*VT_STRIDE)        // 512
#define PCH_OFF  (PB_OFF + 512)                  // 16*128 = 2048
#define MS_OFF   (PCH_OFF + 2048)                // 32 tp * 130 * 2 = 8320
#define SMEM_ATT_FLOATS (MS_OFF + 32*130*2)
#define SMEM_ATT_BYTES  (SMEM_ATT_FLOATS * 4)

__global__ void __launch_bounds__(256, 2) k_attention(
    const float* __restrict__ x, const float* __restrict__ Wc,
    const float* __restrict__ bc, const float* __restrict__ ginw,
    const float* __restrict__ ginb) {
    extern __shared__ float sm[];
    float* sx   = sm + SX_OFF;
    float* vTf  = sm + VT_OFF;
    float* pbuf = sm + PB_OFF;
    float* Pch  = sm + PCH_OFF;
    float* MsF  = sm + MS_OFF;
    const int tid = threadIdx.x;
    const int b = blockIdx.x;

    // stage x[b] (600 floats)
    for (int i = tid; i < 150; i += 256)
        ((float4*)sx)[i] = ((const float4*)(x + (size_t)b * 600))[i];
    __syncthreads();

    // ---- conv1x1 + GroupNorm(16 groups), thread = channel ----
    {
        const int c = tid;
        float wr[10];
        #pragma unroll
        for (int i = 0; i < 10; ++i) wr[i] = Wc[c * 10 + i];
        const float bb = bc[c];
        float s1 = 0.f, s2 = 0.f;
        float* vrow = vTf + c * VT_STRIDE;
        #pragma unroll 4
        for (int t = 0; t < 60; ++t) {
            const float* xr = sx + t * 10;
            float h = bb;
            #pragma unroll
            for (int i = 0; i < 10; ++i) h = fmaf(wr[i], xr[i], h);
            vrow[t] = h; s1 += h; s2 = fmaf(h, h, s2);
        }
        #pragma unroll
        for (int o = 8; o; o >>= 1) {
            s1 += __shfl_xor_sync(0xffffffffu, s1, o);
            s2 += __shfl_xor_sync(0xffffffffu, s2, o);
        }
        float mean = s1 * (1.f / 960.f);
        float var = s2 * (1.f / 960.f) - mean * mean;
        float sc = ginw[c] * rsqrtf(var + EPSF);
        float sh = ginb[c] - mean * sc;
        #pragma unroll 4
        for (int t = 0; t < 60; ++t) vrow[t] = fmaf(vrow[t], sc, sh);
        vrow[60] = vrow[61] = vrow[62] = vrow[63] = 0.f;
    }

    const int e0 = (b * 13) >> 10;
    const int e12 = (b * 13 + 12) >> 10;
    const int nchunks = (e0 == e12) ? 2 : 4;
    const int w = tid >> 5;        // warp id (t-group in GEMM, hk-lane in epilogue)
    const int lane = tid & 31;

    for (int chunk = 0; chunk < nchunks; ++chunk) {
        // ---- GEMM: Ms[t][w16+a] = sum_c v[t][c] * P[c][col] for this chunk ----
        ull acc[4][4];
        #pragma unroll
        for (int i = 0; i < 4; ++i)
            #pragma unroll
            for (int j = 0; j < 4; ++j) acc[i][j] = 0ull;

        for (int c0 = 0; c0 < 256; c0 += 16) {
            __syncthreads();
            // stage P chunk [16 c][128 col]
            #pragma unroll
            for (int rr = 0; rr < 2; ++rr) {
                int q = tid + rr * 256;
                int c = q >> 5, s = (q >> 2) & 7, fq = q & 3;
                int S = chunk * 8 + s;
                int mm = (S < 16) ? (S * 13 + e0) : ((S - 16) * 13 + e0 + 1);
                float4 pv = *(const float4*)(g_P + (size_t)(c0 + c) * 3328 + mm * 16 + fq * 4);
                *(float4*)(Pch + c * 128 + s * 16 + fq * 4) = pv;
            }
            __syncthreads();
            #pragma unroll
            for (int kk = 0; kk < 16; ++kk) {
                const float* vb = vTf + (c0 + kk) * VT_STRIDE + w * 8;
                ull v0 = *(const ull*)(vb);
                ull v1 = *(const ull*)(vb + 2);
                ull v2 = *(const ull*)(vb + 4);
                ull v3 = *(const ull*)(vb + 6);
                float4 pp = *(const float4*)(Pch + kk * 128 + lane * 4);
                ull p0 = dup2(pp.x), p1 = dup2(pp.y), p2 = dup2(pp.z), p3 = dup2(pp.w);
                acc[0][0] = fma2(v0, p0, acc[0][0]);
                acc[0][1] = fma2(v0, p1, acc[0][1]);
                acc[0][2] = fma2(v0, p2, acc[0][2]);
                acc[0][3] = fma2(v0, p3, acc[0][3]);
                acc[1][0] = fma2(v1, p0, acc[1][0]);
                acc[1][1] = fma2(v1, p1, acc[1][1]);
                acc[1][2] = fma2(v1, p2, acc[1][2]);
                acc[1][3] = fma2(v1, p3, acc[1][3]);
                acc[2][0] = fma2(v2, p0, acc[2][0]);
                acc[2][1] = fma2(v2, p1, acc[2][1]);
                acc[2][2] = fma2(v2, p2, acc[2][2]);
                acc[2][3] = fma2(v2, p3, acc[2][3]);
                acc[3][0] = fma2(v3, p0, acc[3][0]);
                acc[3][1] = fma2(v3, p1, acc[3][1]);
                acc[3][2] = fma2(v3, p2, acc[3][2]);
                acc[3][3] = fma2(v3, p3, acc[3][3]);
            }
        }
        // write Ms (float2 over t-pairs), chunk-local cols 0..127
        #pragma unroll
        for (int i = 0; i < 4; ++i) {
            int tp = w * 4 + i;
            #pragma unroll
            for (int j = 0; j < 4; ++j) {
                int col = lane * 4 + j;
                *(ull*)(MsF + 2 * (tp * 130 + col)) = acc[i][j];
            }
        }
        __syncthreads();

        // ---- epilogue for this chunk: warp w owns hk = (chunk&1)*8 + w ----
        const int ec = e0 + (chunk >> 1);
        const int hk = ((chunk & 1) << 3) + w;
        for (int j = 0; j < 13; ++j) {
            int e = (b * 13 + j) >> 10;
            if (e != ec) continue;
            int m = hk * 13 + e;
            int val = j * 240 + lane * 4;
            int t = val / 52;
            int a = (val - t * 52) >> 2;
            float l1 = MsF[2 * ((t >> 1) * 130 + w * 16 + a) + (t & 1)] + g_Pb[m * 16 + a];
            float l2 = -1e30f;
            if (lane < 28) {
                int val2 = val + 128;
                int t2 = val2 / 52;
                int a2 = (val2 - t2 * 52) >> 2;
                l2 = MsF[2 * ((t2 >> 1) * 130 + w * 16 + a2) + (t2 & 1)] + g_Pb[m * 16 + a2];
            }
            float mx = fmaxf(l1, l2);
            #pragma unroll
            for (int o = 16; o; o >>= 1) mx = fmaxf(mx, __shfl_xor_sync(0xffffffffu, mx, o));
            float x1 = __expf(l1 - mx);
            float x2 = (lane < 28) ? __expf(l2 - mx) : 0.f;
            float sum = x1 + x2;
            #pragma unroll
            for (int o = 16; o; o >>= 1) sum += __shfl_xor_sync(0xffffffffu, sum, o);
            float inv = 1.f / sum;
            pbuf[w * 64 + lane] = x1 * inv;
            if (lane < 28) pbuf[w * 64 + 32 + lane] = x2 * inv;
            __syncwarp();
            // AV: lanes 0..15 sum t 0..29, lanes 16..31 sum t 30..59
            int dh = lane & 15;
            int toff = (lane >> 4) * 30;
            const float* vcol = vTf + (hk * 16 + dh) * VT_STRIDE + toff;
            const float* pb = pbuf + w * 64 + toff;
            float acv = 0.f;
            #pragma unroll 6
            for (int tt = 0; tt < 30; ++tt) acv = fmaf(pb[tt], vcol[tt], acv);
            acv += __shfl_xor_sync(0xffffffffu, acv, 16);
            if (lane < 16) {
                int bq = (b * 13 + j) & 1023;
                g_att[(size_t)((m >> 4) * 1024 + bq) * 256 + ((m & 15) << 4) + dh] = acv;
            }
            __syncwarp();
        }
    }
}

// ================= MLP + BN + ReLU + GroupNorm + permute =================
// 104 blocks x 128 rows; thread = (rq = tid>>3) x (fg = tid&7); 4 rows, 16 f each.
#define SO_OFF   0                          // [128][260]
#define SWC_OFF  (128*260)                  // [64][132]
#define SBF_OFF  (SWC_OFF + 64*132)
#define SGW_OFF  (SBF_OFF + 128)
#define SGB_OFF  (SGW_OFF + 128)
#define SMEM_MLP_FLOATS (SGB_OFF + 128)
#define SMEM_MLP_BYTES  (SMEM_MLP_FLOATS * 4)

__global__ void __launch_bounds__(256, 1) k_mlp(const float* __restrict__ gow,
                                                const float* __restrict__ gob,
                                                float* __restrict__ out) {
    extern __shared__ float sm[];
    float* sO  = sm + SO_OFF;
    float* sW  = sm + SWC_OFF;
    float* sBF = sm + SBF_OFF;
    float* sGW = sm + SGW_OFF;
    float* sGB = sm + SGB_OFF;
    const int tid = threadIdx.x;
    const int row0 = blockIdx.x * 128;

    // stage O tile [128][256] -> [128][260]
    for (int q = tid; q < 8192; q += 256) {
        int row = q >> 6, c4 = q & 63;
        *(float4*)(sO + row * 260 + c4 * 4) =
            *(const float4*)(g_att + (size_t)(row0 + row) * 256 + c4 * 4);
    }
    if (tid < 128) { sBF[tid] = g_bf[tid]; sGW[tid] = gow[tid]; sGB[tid] = gob[tid]; }

    const int rq = tid >> 3;       // 0..31
    const int fg = tid & 7;        // f = 16k + fg*2 + {0,1}
    ull acc[4][8];
    #pragma unroll
    for (int i = 0; i < 4; ++i)
        #pragma unroll
        for (int k = 0; k < 8; ++k) acc[i][k] = 0ull;

    for (int cc = 0; cc < 4; ++cc) {
        __syncthreads();
        for (int q = tid; q < 2048; q += 256) {
            int c = q >> 5, f4 = q & 31;
            *(float4*)(sW + c * 132 + f4 * 4) =
                *(const float4*)(g_W1T + (size_t)(cc * 64 + c) * 128 + f4 * 4);
        }
        __syncthreads();
        #pragma unroll 4
        for (int c = 0; c < 64; ++c) {
            const float* wr = sW + c * 132 + fg * 2;
            ull wv[8];
            #pragma unroll
            for (int k = 0; k < 8; ++k) wv[k] = *(const ull*)(wr + 16 * k);
            int cg = cc * 64 + c;
            #pragma unroll
            for (int i = 0; i < 4; ++i) {
                ull od = dup2(sO[(rq + 32 * i) * 260 + cg]);
                #pragma unroll
                for (int k = 0; k < 8; ++k)
                    acc[i][k] = fma2(od, wv[k], acc[i][k]);
            }
        }
    }

    // bias + relu + GroupNorm + permuted store, per row
    #pragma unroll
    for (int i = 0; i < 4; ++i) {
        int r = row0 + rq + 32 * i;
        float* orow_out = out + (size_t)((r & 1023) * 13 + (r >> 10)) * 128;
        #pragma unroll
        for (int k = 0; k < 8; ++k) {
            int f = 16 * k + fg * 2;
            float y0 = fmaxf(lo32(acc[i][k]) + sBF[f], 0.f);
            float y1 = fmaxf(hi32(acc[i][k]) + sBF[f + 1], 0.f);
            float s = y0 + y1;
            float s2 = y0 * y0 + y1 * y1;
            s  += __shfl_xor_sync(0xffffffffu, s, 1);
            s2 += __shfl_xor_sync(0xffffffffu, s2, 1);
            s  += __shfl_xor_sync(0xffffffffu, s, 2);
            s2 += __shfl_xor_sync(0xffffffffu, s2, 2);
            float mean = s * 0.125f;
            float var = s2 * 0.125f - mean * mean;
            float sc = rsqrtf(var + EPSF);
            float o0 = (y0 - mean) * sc * sGW[f] + sGB[f];
            float o1 = (y1 - mean) * sc * sGW[f + 1] + sGB[f + 1];
            *(float2*)(orow_out + f) = make_float2(o0, o1);
        }
    }
}

// ================= launch =================
extern "C" void kernel_launch(void* const* d_in, const int* in_sizes, int n_in,
                              void* d_out, int out_size) {
    (void)in_sizes; (void)n_in; (void)out_size;
    const float* x    = (const float*)d_in[0];
    const float* Wc   = (const float*)d_in[1];
    const float* bc   = (const float*)d_in[2];
    const float* ginw = (const float*)d_in[3];
    const float* ginb = (const float*)d_in[4];
    const float* Q    = (const float*)d_in[5];
    const float* Wk   = (const float*)d_in[6];
    const float* bk   = (const float*)d_in[7];
    const float* W1   = (const float*)d_in[8];
    const float* b1   = (const float*)d_in[9];
    const float* bnw  = (const float*)d_in[10];
    const float* bnb  = (const float*)d_in[11];
    const float* bnrm = (const float*)d_in[12];
    const float* bnrv = (const float*)d_in[13];
    const float* gow  = (const float*)d_in[14];
    const float* gob  = (const float*)d_in[15];
    float* out = (float*)d_out;

    cudaFuncSetAttribute(k_attention, cudaFuncAttributeMaxDynamicSharedMemorySize, SMEM_ATT_BYTES);
    cudaFuncSetAttribute(k_mlp, cudaFuncAttributeMaxDynamicSharedMemorySize, SMEM_MLP_BYTES);

    k_precompP<<<208, 256>>>(Q, Wk, bk);
    k_foldW1<<<128, 256>>>(W1, b1, bnw, bnb, bnrm, bnrv);
    k_attention<<<1024, 256, SMEM_ATT_BYTES>>>(x, Wc, bc, ginw, ginb);
    k_mlp<<<104, 256, SMEM_MLP_BYTES>>>(gow, gob, out);
}